// round 2
// baseline (speedup 1.0000x reference)
#include <cuda_runtime.h>

#define Bn 2
#define Cn 64
#define Hn 128
#define Wn 256
#define Nn (Hn * Wn)   // 32768
#define Kn 32

// Scratch (static __device__ — no allocations allowed).
// g_kv[b][n][0..63] = key channels (from S), [64..127] = value channels (from R)
__device__ float g_kv[(size_t)Bn * Nn * 2 * Cn];   // 33.5 MB
__device__ float g_qt[(size_t)Bn * Nn * Cn];       // 16.8 MB

// ---------------------------------------------------------------------------
// Kernel 1: [B,C,N] -> [B,N,C] transposes for S,R (interleaved into g_kv) and Q.
// blockDim (32,8); grid (N/32, 6, B). sel: 0-1 = S halves, 2-3 = R halves, 4-5 = Q halves.
// ---------------------------------------------------------------------------
__global__ void transpose_kernel(const float* __restrict__ S,
                                 const float* __restrict__ R,
                                 const float* __restrict__ Q) {
    __shared__ float tile[32][33];
    const int b   = blockIdx.z;
    const int sel = blockIdx.y;
    const int n0  = blockIdx.x * 32;
    const int tx = threadIdx.x, ty = threadIdx.y;

    const float* src; int c0; float* dst; int cbase; int cstride;
    if (sel < 2)      { src = S; c0 = sel * 32;       dst = g_kv; cbase = sel * 32;            cstride = 128; }
    else if (sel < 4) { src = R; c0 = (sel - 2) * 32; dst = g_kv; cbase = 64 + (sel - 2) * 32; cstride = 128; }
    else              { src = Q; c0 = (sel - 4) * 32; dst = g_qt; cbase = (sel - 4) * 32;      cstride = 64;  }

    const float* sp = src + (size_t)b * Cn * Nn;
    #pragma unroll
    for (int r = 0; r < 4; r++) {
        int c = c0 + ty + r * 8;
        tile[ty + r * 8][tx] = sp[(size_t)c * Nn + n0 + tx];
    }
    __syncthreads();
    float* dp = dst + (size_t)b * Nn * cstride;
    #pragma unroll
    for (int r = 0; r < 4; r++) {
        int n = n0 + ty + r * 8;
        dp[(size_t)n * cstride + cbase + tx] = tile[tx][ty + r * 8];
    }
}

// ---------------------------------------------------------------------------
// Kernel 2: one warp per (b,n). Lane owns channels (2*lane, 2*lane+1) as float2
// and candidate k = lane's position. Two passes over k: scores, then values.
// Coalesced output via per-block smem transpose (8 consecutive n per block).
// ---------------------------------------------------------------------------
__global__ void __launch_bounds__(256)
attn_kernel(const int* __restrict__ Px,
            const int* __restrict__ Py,
            float* __restrict__ out) {
    const int warp = threadIdx.x >> 5;
    const int lane = threadIdx.x & 31;
    const int gidx = blockIdx.x * 8 + warp;     // = b*N + n
    const int b = gidx >> 15;
    const int n = gidx & (Nn - 1);
    const unsigned FULL = 0xffffffffu;

    // Lane l owns candidate l's position.
    const int pos = Px[n * Kn + lane] * Wn + Py[n * Kn + lane];

    const float* kvb = g_kv + (size_t)b * Nn * 128;
    const float2 q = ((const float2*)(g_qt + ((size_t)b * Nn + n) * 64))[lane];

    // ---- Pass 1: scores ----
    float my_score = 0.f;
    #pragma unroll 8
    for (int k = 0; k < Kn; k++) {
        int p = __shfl_sync(FULL, pos, k);
        float2 kv = ((const float2*)(kvb + (size_t)p * 128))[lane];
        float partial = q.x * kv.x + q.y * kv.y;
        #pragma unroll
        for (int o = 16; o; o >>= 1) partial += __shfl_xor_sync(FULL, partial, o);
        if (lane == k) my_score = partial;
    }

    // ---- Softmax across lanes (lane l holds score_l) ----
    float m = my_score;
    #pragma unroll
    for (int o = 16; o; o >>= 1) m = fmaxf(m, __shfl_xor_sync(FULL, m, o));
    float e = __expf(my_score - m);
    float s = e;
    #pragma unroll
    for (int o = 16; o; o >>= 1) s += __shfl_xor_sync(FULL, s, o);
    const float w = e / s;

    // ---- Pass 2: weighted values ----
    float accx = 0.f, accy = 0.f;
    #pragma unroll 8
    for (int k = 0; k < Kn; k++) {
        int p  = __shfl_sync(FULL, pos, k);
        float wk = __shfl_sync(FULL, w, k);
        float2 v = ((const float2*)(kvb + (size_t)p * 128 + 64))[lane];
        accx += wk * v.x;
        accy += wk * v.y;
    }

    // ---- Coalesced store: smem transpose within block (8 consecutive n, same b) ----
    __shared__ float so[8][65];
    so[warp][2 * lane]     = accx;
    so[warp][2 * lane + 1] = accy;
    __syncthreads();

    const int nb    = blockIdx.x * 8;
    const int bb    = nb >> 15;
    const int nbase = nb & (Nn - 1);
    const int t = threadIdx.x;
    #pragma unroll
    for (int e2 = 0; e2 < 2; e2++) {
        int idx = t + e2 * 256;
        int c = idx >> 3, i = idx & 7;
        out[((size_t)(bb * Cn + c)) * Nn + nbase + i] = so[i][c];
    }
}

// ---------------------------------------------------------------------------
// Inputs (metadata order): Q f32, S f32, R f32, Pos_x i32, Pos_y i32
// ---------------------------------------------------------------------------
extern "C" void kernel_launch(void* const* d_in, const int* in_sizes, int n_in,
                              void* d_out, int out_size) {
    const float* Q  = (const float*)d_in[0];
    const float* S  = (const float*)d_in[1];
    const float* R  = (const float*)d_in[2];
    const int*   Px = (const int*)d_in[3];
    const int*   Py = (const int*)d_in[4];
    float* out = (float*)d_out;

    dim3 tgrid(Nn / 32, 6, Bn);
    dim3 tblk(32, 8);
    transpose_kernel<<<tgrid, tblk>>>(S, R, Q);

    attn_kernel<<<(Bn * Nn) / 8, 256>>>(Px, Py, out);
}

// round 4
// speedup vs baseline: 1.5425x; 1.5425x over previous
#include <cuda_runtime.h>

#define Bn 2
#define Cn 64
#define Hn 128
#define Wn 256
#define Nn (Hn * Wn)   // 32768
#define Kn 32

// Scratch (static __device__ — no allocations allowed).
// g_kv[b][n][0..63] = key channels (from S), [64..127] = value channels (from R)
__device__ float g_kv[(size_t)Bn * Nn * 2 * Cn];   // 33.5 MB
__device__ float g_qt[(size_t)Bn * Nn * Cn];       // 16.8 MB

// ---------------------------------------------------------------------------
// Kernel 1: [B,C,N] -> [B,N,C] transposes for S,R (interleaved into g_kv) and Q.
// blockDim (32,8); grid (N/32, 6, B). sel: 0-1 = S halves, 2-3 = R halves, 4-5 = Q halves.
// ---------------------------------------------------------------------------
__global__ void transpose_kernel(const float* __restrict__ S,
                                 const float* __restrict__ R,
                                 const float* __restrict__ Q) {
    __shared__ float tile[32][33];
    const int b   = blockIdx.z;
    const int sel = blockIdx.y;
    const int n0  = blockIdx.x * 32;
    const int tx = threadIdx.x, ty = threadIdx.y;

    const float* src; int c0; float* dst; int cbase; int cstride;
    if (sel < 2)      { src = S; c0 = sel * 32;       dst = g_kv; cbase = sel * 32;            cstride = 128; }
    else if (sel < 4) { src = R; c0 = (sel - 2) * 32; dst = g_kv; cbase = 64 + (sel - 2) * 32; cstride = 128; }
    else              { src = Q; c0 = (sel - 4) * 32; dst = g_qt; cbase = (sel - 4) * 32;      cstride = 64;  }

    const float* sp = src + (size_t)b * Cn * Nn;
    #pragma unroll
    for (int r = 0; r < 4; r++) {
        int c = c0 + ty + r * 8;
        tile[ty + r * 8][tx] = sp[(size_t)c * Nn + n0 + tx];
    }
    __syncthreads();
    float* dp = dst + (size_t)b * Nn * cstride;
    #pragma unroll
    for (int r = 0; r < 4; r++) {
        int n = n0 + ty + r * 8;
        dp[(size_t)n * cstride + cbase + tx] = tile[tx][ty + r * 8];
    }
}

// ---------------------------------------------------------------------------
// Kernel 2: one warp per (b,n).
//  - Lane l owns candidate l's position.
//  - Gathers are float4, half-warp per candidate: lanes 0-15 load candidate t,
//    lanes 16-31 load candidate t+16 in the SAME LDG.128 (channels 4*(lane&15)).
//  - Scores: each lane keeps 16 partials, then a 4-round butterfly
//    transpose-reduce (15 shfls) lands candidate l's score on lane l.
//  - Softmax across lanes, then pass 2 gathers values the same way and merges
//    the two half-warp accumulators with 4 xor-16 shfls.
// ---------------------------------------------------------------------------
__global__ void __launch_bounds__(256)
attn_kernel(const int* __restrict__ Px,
            const int* __restrict__ Py,
            float* __restrict__ out) {
    const int warp = threadIdx.x >> 5;
    const int lane = threadIdx.x & 31;
    const int gidx = blockIdx.x * 8 + warp;     // = b*N + n
    const int b = gidx >> 15;
    const int n = gidx & (Nn - 1);
    const unsigned FULL = 0xffffffffu;

    const int baseLane = lane & 16;             // half-warp selector
    const int ch4 = (lane & 15) * 4;            // this lane's 4 channels

    // Lane l owns candidate l's position.
    const int pos = Px[n * Kn + lane] * Wn + Py[n * Kn + lane];

    const float* kvb = g_kv + (size_t)b * Nn * 128;
    const float4 q = *(const float4*)(g_qt + ((size_t)b * Nn + n) * 64 + ch4);

    // ---- Pass 1: partial scores. v[t] = dot4 of my 4 channels with candidate
    //      (baseLane + t)'s key.
    float v[16];
    #pragma unroll
    for (int t = 0; t < 16; t++) {
        int p = __shfl_sync(FULL, pos, baseLane + t);
        const float4 kk = *(const float4*)(kvb + (size_t)p * 128 + ch4);
        v[t] = q.x * kk.x + q.y * kk.y + q.z * kk.z + q.w * kk.w;
    }

    // ---- Butterfly transpose-reduce within each 16-lane half (15 shfls).
    //      After this, lane l holds the full score of candidate l in v[0].
    #pragma unroll
    for (int o = 8; o >= 1; o >>= 1) {
        #pragma unroll
        for (int j = 0; j < 8; j++) {
            if (j < o) {
                float send = (lane & o) ? v[j] : v[j + o];
                float recv = __shfl_xor_sync(FULL, send, o);
                v[j] = ((lane & o) ? v[j + o] : v[j]) + recv;
            }
        }
    }
    float my_score = v[0];

    // ---- Softmax across 32 lanes (lane l holds score of candidate l) ----
    float m = my_score;
    #pragma unroll
    for (int o = 16; o; o >>= 1) m = fmaxf(m, __shfl_xor_sync(FULL, m, o));
    float e = __expf(my_score - m);
    float s = e;
    #pragma unroll
    for (int o = 16; o; o >>= 1) s += __shfl_xor_sync(FULL, s, o);
    const float w = e / s;

    // ---- Pass 2: weighted values, half-warp per candidate ----
    float4 acc = make_float4(0.f, 0.f, 0.f, 0.f);
    #pragma unroll
    for (int t = 0; t < 16; t++) {
        int   p  = __shfl_sync(FULL, pos, baseLane + t);
        float wk = __shfl_sync(FULL, w,   baseLane + t);
        const float4 vv = *(const float4*)(kvb + (size_t)p * 128 + 64 + ch4);
        acc.x += wk * vv.x;
        acc.y += wk * vv.y;
        acc.z += wk * vv.z;
        acc.w += wk * vv.w;
    }
    // Merge lower-half (candidates 0-15) and upper-half (16-31) accumulators.
    acc.x += __shfl_xor_sync(FULL, acc.x, 16);
    acc.y += __shfl_xor_sync(FULL, acc.y, 16);
    acc.z += __shfl_xor_sync(FULL, acc.z, 16);
    acc.w += __shfl_xor_sync(FULL, acc.w, 16);

    // ---- Coalesced store: smem transpose within block (8 consecutive n) ----
    __shared__ float so[8][68];                 // 68-float row stride (16B-aligned, conflict-free)
    if (lane < 16) {
        *(float4*)&so[warp][ch4] = acc;
    }
    __syncthreads();

    const int nb    = blockIdx.x * 8;
    const int bb    = nb >> 15;
    const int nbase = nb & (Nn - 1);
    const int t = threadIdx.x;
    #pragma unroll
    for (int e2 = 0; e2 < 2; e2++) {
        int idx = t + e2 * 256;
        int c = idx >> 3, i = idx & 7;
        out[((size_t)(bb * Cn + c)) * Nn + nbase + i] = so[i][c];
    }
}

// ---------------------------------------------------------------------------
// Inputs (metadata order): Q f32, S f32, R f32, Pos_x i32, Pos_y i32
// ---------------------------------------------------------------------------
extern "C" void kernel_launch(void* const* d_in, const int* in_sizes, int n_in,
                              void* d_out, int out_size) {
    const float* Q  = (const float*)d_in[0];
    const float* S  = (const float*)d_in[1];
    const float* R  = (const float*)d_in[2];
    const int*   Px = (const int*)d_in[3];
    const int*   Py = (const int*)d_in[4];
    float* out = (float*)d_out;

    dim3 tgrid(Nn / 32, 6, Bn);
    dim3 tblk(32, 8);
    transpose_kernel<<<tgrid, tblk>>>(S, R, Q);

    attn_kernel<<<(Bn * Nn) / 8, 256>>>(Px, Py, out);
}

// round 5
// speedup vs baseline: 1.6368x; 1.0611x over previous
#include <cuda_runtime.h>
#include <cuda_fp16.h>

#define Bn 2
#define Cn 64
#define Hn 128
#define Wn 256
#define Nn (Hn * Wn)   // 32768
#define Kn 32

// Scratch (static __device__ — no allocations allowed).
// Per-position 384-byte record: bytes [0,256) = 64 f32 key channels (from S),
// bytes [256,384) = 64 f16 value channels (from R). 384 = 3*128 keeps both
// segments 128B-line aligned.
#define REC 384
__device__ __align__(16) unsigned char g_kv[(size_t)Bn * Nn * REC];  // 25.2 MB
__device__ float g_qt[(size_t)Bn * Nn * Cn];                          // 16.8 MB

// ---------------------------------------------------------------------------
// Kernel 1: [B,C,N] -> [B,N,*] transposes. S -> f32 keys, R -> f16 values,
// Q -> f32 g_qt. blockDim (32,8); grid (N/32, 6, B).
// sel: 0-1 = S halves, 2-3 = R halves, 4-5 = Q halves.
// ---------------------------------------------------------------------------
__global__ void transpose_kernel(const float* __restrict__ S,
                                 const float* __restrict__ R,
                                 const float* __restrict__ Q) {
    __shared__ float tile[32][33];
    const int b   = blockIdx.z;
    const int sel = blockIdx.y;
    const int n0  = blockIdx.x * 32;
    const int tx = threadIdx.x, ty = threadIdx.y;

    const float* src = (sel < 2) ? S : (sel < 4) ? R : Q;
    const int    c0  = (sel & 1) * 32;          // sel 0,2,4 -> 0 ; 1,3,5 -> 32

    const float* sp = src + (size_t)b * Cn * Nn;
    #pragma unroll
    for (int r = 0; r < 4; r++) {
        int c = c0 + ty + r * 8;
        tile[ty + r * 8][tx] = sp[(size_t)c * Nn + n0 + tx];
    }
    __syncthreads();

    #pragma unroll
    for (int r = 0; r < 4; r++) {
        int n = n0 + ty + r * 8;
        float val = tile[tx][ty + r * 8];
        if (sel < 2) {            // key: f32 at record byte 0
            float* rowf = (float*)(g_kv + ((size_t)b * Nn + n) * REC);
            rowf[c0 + tx] = val;
        } else if (sel < 4) {     // value: f16 at record byte 256
            __half* rowh = (__half*)(g_kv + ((size_t)b * Nn + n) * REC + 256);
            rowh[c0 + tx] = __float2half(val);
        } else {                  // Q: f32, stride 64
            g_qt[((size_t)b * Nn + n) * 64 + c0 + tx] = val;
        }
    }
}

// ---------------------------------------------------------------------------
// Kernel 2: one warp per (b,n).
//  - Lane l owns candidate l's position.
//  - Key gather: float4, half-warp per candidate (lanes 0-15 -> cand t,
//    lanes 16-31 -> cand t+16; channels 4*(lane&15)).
//  - Value gather: 8B (4 x f16) per lane -> one fully-consumed 128B line
//    per candidate.
//  - Scores: 16 register partials + 4-round butterfly transpose-reduce
//    (15 shfls) lands candidate l's score on lane l.
// ---------------------------------------------------------------------------
__global__ void __launch_bounds__(256)
attn_kernel(const int* __restrict__ Px,
            const int* __restrict__ Py,
            float* __restrict__ out) {
    const int warp = threadIdx.x >> 5;
    const int lane = threadIdx.x & 31;
    const int gidx = blockIdx.x * 8 + warp;     // = b*N + n
    const int b = gidx >> 15;
    const int n = gidx & (Nn - 1);
    const unsigned FULL = 0xffffffffu;

    const int baseLane = lane & 16;             // half-warp selector
    const int l15 = lane & 15;
    const int ch4 = l15 * 4;                    // this lane's 4 channels

    // Lane l owns candidate l's position.
    const int pos = Px[n * Kn + lane] * Wn + Py[n * Kn + lane];

    const unsigned char* kvb = g_kv + (size_t)b * Nn * REC;
    const float4 q = *(const float4*)(g_qt + ((size_t)b * Nn + n) * 64 + ch4);

    // ---- Pass 1: partial scores ----
    float v[16];
    #pragma unroll
    for (int t = 0; t < 16; t++) {
        int p = __shfl_sync(FULL, pos, baseLane + t);
        const float4 kk = *(const float4*)(kvb + (size_t)p * REC + ch4 * 4);
        v[t] = q.x * kk.x + q.y * kk.y + q.z * kk.z + q.w * kk.w;
    }

    // ---- Butterfly transpose-reduce within each 16-lane half (15 shfls).
    //      After this, lane l holds the full score of candidate l in v[0].
    #pragma unroll
    for (int o = 8; o >= 1; o >>= 1) {
        #pragma unroll
        for (int j = 0; j < 8; j++) {
            if (j < o) {
                float send = (lane & o) ? v[j] : v[j + o];
                float recv = __shfl_xor_sync(FULL, send, o);
                v[j] = ((lane & o) ? v[j + o] : v[j]) + recv;
            }
        }
    }
    float my_score = v[0];

    // ---- Softmax across 32 lanes (lane l holds score of candidate l) ----
    float m = my_score;
    #pragma unroll
    for (int o = 16; o; o >>= 1) m = fmaxf(m, __shfl_xor_sync(FULL, m, o));
    float e = __expf(my_score - m);
    float s = e;
    #pragma unroll
    for (int o = 16; o; o >>= 1) s += __shfl_xor_sync(FULL, s, o);
    const float w = e / s;

    // ---- Pass 2: weighted f16 values (fp32 accumulate) ----
    float4 acc = make_float4(0.f, 0.f, 0.f, 0.f);
    #pragma unroll
    for (int t = 0; t < 16; t++) {
        int   p  = __shfl_sync(FULL, pos, baseLane + t);
        float wk = __shfl_sync(FULL, w,   baseLane + t);
        uint2 raw = *(const uint2*)(kvb + (size_t)p * REC + 256 + l15 * 8);
        float2 f01 = __half22float2(*reinterpret_cast<__half2*>(&raw.x));
        float2 f23 = __half22float2(*reinterpret_cast<__half2*>(&raw.y));
        acc.x += wk * f01.x;
        acc.y += wk * f01.y;
        acc.z += wk * f23.x;
        acc.w += wk * f23.y;
    }
    // Merge lower-half (candidates 0-15) and upper-half (16-31) accumulators.
    acc.x += __shfl_xor_sync(FULL, acc.x, 16);
    acc.y += __shfl_xor_sync(FULL, acc.y, 16);
    acc.z += __shfl_xor_sync(FULL, acc.z, 16);
    acc.w += __shfl_xor_sync(FULL, acc.w, 16);

    // ---- Coalesced store: smem transpose within block (8 consecutive n) ----
    __shared__ float so[8][68];                 // 16B-aligned rows, conflict-free
    if (lane < 16) {
        *(float4*)&so[warp][ch4] = acc;
    }
    __syncthreads();

    const int nb    = blockIdx.x * 8;
    const int bb    = nb >> 15;
    const int nbase = nb & (Nn - 1);
    const int t = threadIdx.x;
    #pragma unroll
    for (int e2 = 0; e2 < 2; e2++) {
        int idx = t + e2 * 256;
        int c = idx >> 3, i = idx & 7;
        out[((size_t)(bb * Cn + c)) * Nn + nbase + i] = so[i][c];
    }
}

// ---------------------------------------------------------------------------
// Inputs (metadata order): Q f32, S f32, R f32, Pos_x i32, Pos_y i32
// ---------------------------------------------------------------------------
extern "C" void kernel_launch(void* const* d_in, const int* in_sizes, int n_in,
                              void* d_out, int out_size) {
    const float* Q  = (const float*)d_in[0];
    const float* S  = (const float*)d_in[1];
    const float* R  = (const float*)d_in[2];
    const int*   Px = (const int*)d_in[3];
    const int*   Py = (const int*)d_in[4];
    float* out = (float*)d_out;

    dim3 tgrid(Nn / 32, 6, Bn);
    dim3 tblk(32, 8);
    transpose_kernel<<<tgrid, tblk>>>(S, R, Q);

    attn_kernel<<<(Bn * Nn) / 8, 256>>>(Px, Py, out);
}

// round 8
// speedup vs baseline: 1.6738x; 1.0226x over previous
#include <cuda_runtime.h>
#include <cuda_fp16.h>

#define Bn 2
#define Cn 64
#define Hn 128
#define Wn 256
#define Nn (Hn * Wn)   // 32768
#define Kn 32

// Scratch (static __device__ — no allocations allowed).
// Per-position 384-byte record: bytes [0,256) = 64 f32 key channels (from S),
// bytes [256,384) = 64 f16 value channels (from R). 384 = 3*128 keeps both
// segments 128B-line aligned.
#define REC 384
__device__ __align__(16) unsigned char g_kv[(size_t)Bn * Nn * REC];  // 25.2 MB
__device__ float g_qt[(size_t)Bn * Nn * Cn];                          // 16.8 MB

// ---------------------------------------------------------------------------
// Kernel 1: [B,C,N] -> [B,N,*] transposes. S -> f32 keys, R -> f16 values,
// Q -> f32 g_qt. blockDim (32,8); grid (N/32, 6, B).
// sel: 0-1 = S halves, 2-3 = R halves, 4-5 = Q halves.
// ---------------------------------------------------------------------------
__global__ void transpose_kernel(const float* __restrict__ S,
                                 const float* __restrict__ R,
                                 const float* __restrict__ Q) {
    __shared__ float tile[32][33];
    const int b   = blockIdx.z;
    const int sel = blockIdx.y;
    const int n0  = blockIdx.x * 32;
    const int tx = threadIdx.x, ty = threadIdx.y;

    const float* src = (sel < 2) ? S : (sel < 4) ? R : Q;
    const int    c0  = (sel & 1) * 32;          // sel 0,2,4 -> 0 ; 1,3,5 -> 32

    const float* sp = src + (size_t)b * Cn * Nn;
    #pragma unroll
    for (int r = 0; r < 4; r++) {
        int c = c0 + ty + r * 8;
        tile[ty + r * 8][tx] = sp[(size_t)c * Nn + n0 + tx];
    }
    __syncthreads();

    #pragma unroll
    for (int r = 0; r < 4; r++) {
        int n = n0 + ty + r * 8;
        float val = tile[tx][ty + r * 8];
        if (sel < 2) {            // key: f32 at record byte 0
            float* rowf = (float*)(g_kv + ((size_t)b * Nn + n) * REC);
            rowf[c0 + tx] = val;
        } else if (sel < 4) {     // value: f16 at record byte 256
            __half* rowh = (__half*)(g_kv + ((size_t)b * Nn + n) * REC + 256);
            rowh[c0 + tx] = __float2half(val);
        } else {                  // Q: f32, stride 64
            g_qt[((size_t)b * Nn + n) * 64 + c0 + tx] = val;
        }
    }
}

// ---------------------------------------------------------------------------
// Kernel 2: one warp per (b,n).
//  - Lane l owns candidate l's PRE-MULTIPLIED byte offset (pos*REC), so the
//    hot loops shuffle 32-bit byte offsets and do no per-candidate multiply.
//  - Key gather: float4, half-warp per candidate; pass 1 processes candidate
//    pairs (t, t+8) and fuses the xor-8 butterfly round into the loop, so
//    only 8 score partials stay live.
//  - Remaining 3 butterfly rounds (7 shfls) land candidate l's score on lane l.
//  - Value gather: 8B (4 x f16) per lane -> one fully-consumed 128B line per
//    candidate; fp32 accumulate; xor-16 merge.
// ---------------------------------------------------------------------------
__global__ void __launch_bounds__(256, 6)
attn_kernel(const int* __restrict__ Px,
            const int* __restrict__ Py,
            float* __restrict__ out) {
    const int warp = threadIdx.x >> 5;
    const int lane = threadIdx.x & 31;
    const int gidx = blockIdx.x * 8 + warp;     // = b*N + n
    const int b = gidx >> 15;
    const int n = gidx & (Nn - 1);
    const unsigned FULL = 0xffffffffu;

    const int baseLane = lane & 16;             // half-warp selector
    const int l15 = lane & 15;
    const int ch16 = l15 * 16;                  // key byte offset of my 4 channels

    // Lane l owns candidate l's byte offset (pos * REC, fits in 32 bits).
    const unsigned off = (unsigned)(Px[n * Kn + lane] * Wn + Py[n * Kn + lane]) * REC;

    const unsigned char* kvb = g_kv + (size_t)b * Nn * REC;
    const float4 q = *(const float4*)(g_qt + ((size_t)b * Nn + n) * 64 + l15 * 4);

    // ---- Pass 1: scores for candidate pair (t, t+8); fused xor-8 round ----
    float v[8];
    #pragma unroll
    for (int t = 0; t < 8; t++) {
        unsigned pa = __shfl_sync(FULL, off, baseLane + t);
        unsigned pb = __shfl_sync(FULL, off, baseLane + t + 8);
        const float4 ka = *(const float4*)(kvb + pa + ch16);
        const float4 kb = *(const float4*)(kvb + pb + ch16);
        float a = q.x * ka.x + q.y * ka.y + q.z * ka.z + q.w * ka.w;
        float c = q.x * kb.x + q.y * kb.y + q.z * kb.z + q.w * kb.w;
        float send = (lane & 8) ? a : c;
        float recv = __shfl_xor_sync(FULL, send, 8);
        v[t] = ((lane & 8) ? c : a) + recv;
    }

    // ---- Remaining butterfly rounds o=4,2,1 (7 shfls).
    //      After this, lane l holds the full score of candidate l in v[0].
    #pragma unroll
    for (int o = 4; o >= 1; o >>= 1) {
        #pragma unroll
        for (int j = 0; j < 4; j++) {
            if (j < o) {
                float send = (lane & o) ? v[j] : v[j + o];
                float recv = __shfl_xor_sync(FULL, send, o);
                v[j] = ((lane & o) ? v[j + o] : v[j]) + recv;
            }
        }
    }
    float my_score = v[0];

    // ---- Softmax across 32 lanes (lane l holds score of candidate l) ----
    float m = my_score;
    #pragma unroll
    for (int o = 16; o; o >>= 1) m = fmaxf(m, __shfl_xor_sync(FULL, m, o));
    float e = __expf(my_score - m);
    float s = e;
    #pragma unroll
    for (int o = 16; o; o >>= 1) s += __shfl_xor_sync(FULL, s, o);
    const float w = e / s;

    // ---- Pass 2: weighted f16 values (fp32 accumulate) ----
    float4 acc = make_float4(0.f, 0.f, 0.f, 0.f);
    const unsigned voff = 256 + l15 * 8;
    #pragma unroll
    for (int t = 0; t < 16; t++) {
        unsigned p  = __shfl_sync(FULL, off, baseLane + t);
        float    wk = __shfl_sync(FULL, w,   baseLane + t);
        uint2 raw = *(const uint2*)(kvb + p + voff);
        float2 f01 = __half22float2(*reinterpret_cast<__half2*>(&raw.x));
        float2 f23 = __half22float2(*reinterpret_cast<__half2*>(&raw.y));
        acc.x += wk * f01.x;
        acc.y += wk * f01.y;
        acc.z += wk * f23.x;
        acc.w += wk * f23.y;
    }
    // Merge lower-half (candidates 0-15) and upper-half (16-31) accumulators.
    acc.x += __shfl_xor_sync(FULL, acc.x, 16);
    acc.y += __shfl_xor_sync(FULL, acc.y, 16);
    acc.z += __shfl_xor_sync(FULL, acc.z, 16);
    acc.w += __shfl_xor_sync(FULL, acc.w, 16);

    // ---- Coalesced store: smem transpose within block (8 consecutive n) ----
    __shared__ float so[8][68];                 // 16B-aligned rows, conflict-free
    if (lane < 16) {
        *(float4*)&so[warp][l15 * 4] = acc;
    }
    __syncthreads();

    const int nb    = blockIdx.x * 8;
    const int bb    = nb >> 15;
    const int nbase = nb & (Nn - 1);
    const int t = threadIdx.x;
    #pragma unroll
    for (int e2 = 0; e2 < 2; e2++) {
        int idx = t + e2 * 256;
        int c = idx >> 3, i = idx & 7;
        out[((size_t)(bb * Cn + c)) * Nn + nbase + i] = so[i][c];
    }
}

// ---------------------------------------------------------------------------
// Inputs (metadata order): Q f32, S f32, R f32, Pos_x i32, Pos_y i32
// ---------------------------------------------------------------------------
extern "C" void kernel_launch(void* const* d_in, const int* in_sizes, int n_in,
                              void* d_out, int out_size) {
    const float* Q  = (const float*)d_in[0];
    const float* S  = (const float*)d_in[1];
    const float* R  = (const float*)d_in[2];
    const int*   Px = (const int*)d_in[3];
    const int*   Py = (const int*)d_in[4];
    float* out = (float*)d_out;

    dim3 tgrid(Nn / 32, 6, Bn);
    dim3 tblk(32, 8);
    transpose_kernel<<<tgrid, tblk>>>(S, R, Q);

    attn_kernel<<<(Bn * Nn) / 8, 256>>>(Px, Py, out);
}